// round 10
// baseline (speedup 1.0000x reference)
#include <cuda_runtime.h>

// fusedmax(x) = sparsemax(prox_TV1D(x, alpha=1)), row-wise. B=4096, N=512, fp32.
// 128 blocks x 32 threads; lane = row. ys stride-32 (bank = lane), transposes
// via padded staging tile. Condat scan: straight-line branch-free body, done
// lanes masked, warp-uniform exit vote amortized over 4-wide unroll.
// RLE log -> Michelot sparsemax -> prefetched rebuild.

#define NROWS 4096
#define NCOLS 512
#define ROWS_PER_BLK 32
#define PADS 33
#define YS_FLOATS (NCOLS * 32)
#define STAGE_FLOATS (32 * PADS)
#define SEG_ENTRIES 517
#define SEG_OFF (YS_FLOATS + STAGE_FLOATS)
#define SMEM_BYTES ((SEG_OFF) * 4 + SEG_ENTRIES * 32 * 8)

typedef unsigned long long ull;

__device__ __forceinline__ float frcp_fast(float a) {
    float r;
    asm("rcp.approx.f32 %0, %1;" : "=f"(r) : "f"(a));
    return r;
}

__global__ __launch_bounds__(32, 1)
void fusedmax_kernel(const float* __restrict__ x, float* __restrict__ out) {
    extern __shared__ float smem[];
    float* ys    = smem;                         // [NCOLS][32], stride 32
    float* stage = smem + YS_FLOATS;             // [32][PADS]
    ull*   segb  = (ull*)(smem + SEG_OFF);       // [entry][lane]

    const int lane    = threadIdx.x;
    const int rowBase = blockIdx.x * ROWS_PER_BLK;
    const float lam   = 1.0f;
    const int n       = NCOLS;

    // ---- load + transpose via staging tile (both sides conflict-free) ----
    const float* src = x + (size_t)rowBase * NCOLS;
    for (int t = 0; t < 16; t++) {
        #pragma unroll
        for (int i = 0; i < 32; i++)
            stage[i * PADS + lane] = src[i * NCOLS + t * 32 + lane];
        __syncwarp();
        #pragma unroll
        for (int cl = 0; cl < 32; cl++)
            ys[(t * 32 + cl) * 32 + lane] = stage[lane * PADS + cl];
        __syncwarp();
    }

    float* yl   = ys + lane;                     // yl[c*32] == y[c], bank=lane
    ull*   segl = segb + lane;

    // ---- Condat TV1D: uniform loop, straight-line body, vote per 4 iters ----
    int   k = 0, km = 0, kp = 0;
    float vmin = yl[0] - lam;
    float vmax = vmin + 2.0f * lam;
    float umin = lam, umax = -lam;
    float cnt_f = 1.0f;
    float inv_c = 1.0f;                          // rcp(cnt_f), carried
    float yn = yl[1 * 32];                       // prefetched y[k+1]
    int   nseg = 0;
    bool  done = false;

    do {
        #pragma unroll
        for (int u = 0; u < 4; u++) {
            const float inv_spec = frcp_fast(cnt_f + 1.0f);

            const float ycur = yn;               // y[k+1]
            const bool at_end = (k == n - 1);
            const bool neg = at_end ? (umin < 0.0f)
                                    : (ycur + umin < vmin - lam);
            const bool pos = (!neg) & (at_end ? (umax > 0.0f)
                                              : (ycur + umax > vmax + lam));
            const bool jump = neg | pos;
            const bool fin  = (!jump) & at_end;
            const bool eneg = neg & at_end;
            const bool epos = pos & at_end;

            int nk = neg ? (km + 1) : (pos ? (kp + 1) : (k + 1));
            nk = min(nk, n - 1);

            const float ynk = yl[nk * 32];       // jump path (== ycur if mid)
            yn = yl[min(nk + 1, n - 1) * 32];    // prefetch next

            // --- RLE log: unconditional store, masked bump ---
            const int   e_out = neg ? km : (pos ? kp : (n - 1));
            const float v_out = pos ? vmax
                                    : (fin ? fmaf(umin, inv_c, vmin) : vmin);
            segl[nseg * 32] = ((ull)(unsigned)e_out << 32) |
                              (ull)__float_as_uint(v_out);
            nseg += (int)((jump | fin) & !done);
            done |= fin;

            // --- mid candidates (register-fed) ---
            const float inv_cnt = jump ? 1.0f : inv_spec;
            const float umin_t  = umin + ycur - vmin;
            const float umax_t  = umax + ycur - vmax;
            const bool  c1 = (umin_t >= lam);
            const bool  c2 = (umax_t <= -lam);
            const float vmin_mid = c1 ? fmaf(umin_t - lam, inv_cnt, vmin) : vmin;
            const float umin_mid = c1 ? lam : umin_t;
            const int   km_mid   = c1 ? nk : km;
            const float vmax_mid = c2 ? fmaf(umax_t + lam, inv_cnt, vmax) : vmax;
            const float umax_mid = c2 ? -lam : umax_t;
            const int   kp_mid   = c2 ? nk : kp;

            // --- jump candidates ---
            const float vmin_j = neg ? ynk : (epos ? vmin : ynk - 2.0f * lam);
            const float vmax_j = pos ? ynk : (eneg ? vmax : ynk + 2.0f * lam);
            const float umin_j = epos ? (ynk - lam - vmin) : lam;
            const float umax_j = eneg ? (ynk + lam - vmax) : -lam;
            const int   km_j   = epos ? km : nk;
            const int   kp_j   = eneg ? kp : nk;

            // --- merge ---
            vmin = jump ? vmin_j : vmin_mid;
            vmax = jump ? vmax_j : vmax_mid;
            umin = jump ? umin_j : umin_mid;
            umax = jump ? umax_j : umax_mid;
            km   = jump ? km_j   : km_mid;
            kp   = jump ? kp_j   : kp_mid;
            cnt_f = jump ? 1.0f : (cnt_f + 1.0f);
            inv_c = jump ? 1.0f : inv_spec;
            k    = nk;
        }
    } while (!__all_sync(0xFFFFFFFFu, done));

    // ---- sparsemax tau via Michelot on the RLE segments ----
    float tau;
    {
        float sum = 0.0f;
        int prev = -1;
        for (int j = 0; j < nseg; j++) {
            ull w = segl[j * 32];
            int e = (int)(w >> 32);
            sum += (float)(e - prev) * __uint_as_float((unsigned)w);
            prev = e;
        }
        tau = (sum - 1.0f) * (1.0f / (float)NCOLS);
        int c_prev = n;
        for (int it = 0; it < n; it++) {
            float s = 0.0f;
            int   c = 0;
            int   pr = -1;
            for (int j = 0; j < nseg; j++) {
                ull   w = segl[j * 32];
                int   e = (int)(w >> 32);
                float v = __uint_as_float((unsigned)w);
                int len = e - pr; pr = e;
                bool sup = (v > tau);
                s += sup ? (float)len * v : 0.0f;
                c += sup ? len : 0;
            }
            if (c == c_prev) break;
            tau = (s - 1.0f) / (float)c;
            c_prev = c;
        }
    }

    // ---- reconstruct max(val - tau, 0) into ys (prefetched walk) ----
    {
        int j = 0;
        ull w  = segl[0];
        ull wn = segl[32];
        int   e = (int)(w >> 32);
        float v = __uint_as_float((unsigned)w) - tau;
        for (int c = 0; c < n; c++) {
            yl[c * 32] = fmaxf(v, 0.0f);
            const bool adv = ((c + 1) > e);
            j += (int)adv;
            w = adv ? wn : w;
            e = (int)(w >> 32);
            v = __uint_as_float((unsigned)w) - tau;
            wn = segl[min(j + 1, SEG_ENTRIES - 1) * 32];
        }
    }
    __syncwarp();

    // ---- transpose back via staging + coalesced store ----
    float* dst = out + (size_t)rowBase * NCOLS;
    for (int t = 0; t < 16; t++) {
        #pragma unroll
        for (int cl = 0; cl < 32; cl++)
            stage[lane * PADS + cl] = ys[(t * 32 + cl) * 32 + lane];
        __syncwarp();
        #pragma unroll
        for (int i = 0; i < 32; i++)
            dst[i * NCOLS + t * 32 + lane] = stage[i * PADS + lane];
        __syncwarp();
    }
}

extern "C" void kernel_launch(void* const* d_in, const int* in_sizes, int n_in,
                              void* d_out, int out_size) {
    (void)in_sizes; (void)n_in; (void)out_size;
    const float* x   = (const float*)d_in[0];
    float*       out = (float*)d_out;

    cudaFuncSetAttribute(fusedmax_kernel,
                         cudaFuncAttributeMaxDynamicSharedMemorySize,
                         SMEM_BYTES);
    fusedmax_kernel<<<NROWS / ROWS_PER_BLK, ROWS_PER_BLK, SMEM_BYTES>>>(x, out);
}

// round 11
// speedup vs baseline: 2.0883x; 2.0883x over previous
#include <cuda_runtime.h>

// fusedmax(x) = sparsemax(prox_TV1D(x, alpha=1)), row-wise. B=4096, N=512, fp32.
// 128 blocks x 32 threads; lane = row. ys stride-32 (bank = lane), transposes
// via padded staging tile. Condat scan split hot/end: hot loop (k<n-1) has no
// end-phase logic; end step handles k==n-1 cases and re-enters hot loop.
// RLE log -> Michelot sparsemax -> prefetched rebuild.  (R9 skeleton.)

#define NROWS 4096
#define NCOLS 512
#define ROWS_PER_BLK 32
#define PADS 33
#define YS_FLOATS (NCOLS * 32)
#define STAGE_FLOATS (32 * PADS)
#define SEG_ENTRIES 517
#define SEG_OFF (YS_FLOATS + STAGE_FLOATS)
#define SMEM_BYTES ((SEG_OFF) * 4 + SEG_ENTRIES * 32 * 8)

typedef unsigned long long ull;

__device__ __forceinline__ float frcp_fast(float a) {
    float r;
    asm("rcp.approx.f32 %0, %1;" : "=f"(r) : "f"(a));
    return r;
}

__global__ __launch_bounds__(32, 1)
void fusedmax_kernel(const float* __restrict__ x, float* __restrict__ out) {
    extern __shared__ float smem[];
    float* ys    = smem;                         // [NCOLS][32], stride 32
    float* stage = smem + YS_FLOATS;             // [32][PADS]
    ull*   segb  = (ull*)(smem + SEG_OFF);       // [entry][lane]

    const int lane    = threadIdx.x;
    const int rowBase = blockIdx.x * ROWS_PER_BLK;
    const float lam   = 1.0f;
    const int n       = NCOLS;

    // ---- load + transpose via staging tile (both sides conflict-free) ----
    const float* src = x + (size_t)rowBase * NCOLS;
    for (int t = 0; t < 16; t++) {
        #pragma unroll
        for (int i = 0; i < 32; i++)
            stage[i * PADS + lane] = src[i * NCOLS + t * 32 + lane];
        __syncwarp();
        #pragma unroll
        for (int cl = 0; cl < 32; cl++)
            ys[(t * 32 + cl) * 32 + lane] = stage[lane * PADS + cl];
        __syncwarp();
    }

    float* yl   = ys + lane;                     // yl[c*32] == y[c], bank=lane
    ull*   segl = segb + lane;

    // ---- Condat TV1D: hot loop (k < n-1) + end step (k == n-1) ----
    int   k = 0, km = 0, kp = 0;
    float vmin = yl[0] - lam;
    float vmax = vmin + 2.0f * lam;
    float umin = lam, umax = -lam;
    float cnt_f = 1.0f;
    float yn = yl[1 * 32];                       // y[k+1]
    int   nseg = 0;

    while (true) {
        // -------- hot scan: no end-phase logic --------
        while (k < n - 1) {
            const float inv_spec = frcp_fast(cnt_f + 1.0f);
            const float ycur = yn;               // y[k+1]

            const bool neg  = (ycur + umin < vmin - lam);
            const bool pos  = (!neg) & (ycur + umax > vmax + lam);
            const bool jump = neg | pos;

            const int nk = neg ? (km + 1) : (pos ? (kp + 1) : (k + 1));
            // nk <= n-1 guaranteed (k <= n-2, km,kp <= k)

            const float ynk = yl[nk * 32];       // == ycur for mid lanes
            yn = yl[min(nk + 1, n - 1) * 32];    // prefetch next

            // RLE log: unconditional store, bump on jump
            segl[nseg * 32] =
                ((ull)(unsigned)(neg ? km : kp) << 32) |
                (ull)__float_as_uint(pos ? vmax : vmin);
            nseg += (int)jump;

            // mid candidates (register-fed)
            const float inv_cnt = jump ? 1.0f : inv_spec;
            const float umin_t  = umin + ycur - vmin;
            const float umax_t  = umax + ycur - vmax;
            const bool  c1 = (umin_t >= lam);
            const bool  c2 = (umax_t <= -lam);
            const float vmin_mid = c1 ? fmaf(umin_t - lam, inv_cnt, vmin) : vmin;
            const float umin_mid = c1 ? lam : umin_t;
            const int   km_mid   = c1 ? nk : km;
            const float vmax_mid = c2 ? fmaf(umax_t + lam, inv_cnt, vmax) : vmax;
            const float umax_mid = c2 ? -lam : umax_t;
            const int   kp_mid   = c2 ? nk : kp;

            // merge (interior jump: full reset, no end-phase cases)
            vmin = jump ? (neg ? ynk : ynk - 2.0f * lam) : vmin_mid;
            vmax = jump ? (pos ? ynk : ynk + 2.0f * lam) : vmax_mid;
            umin = jump ? lam  : umin_mid;
            umax = jump ? -lam : umax_mid;
            km   = jump ? nk : km_mid;
            kp   = jump ? nk : kp_mid;
            cnt_f = jump ? 1.0f : (cnt_f + 1.0f);
            k    = nk;
        }

        // -------- end step: k == n-1 --------
        if (umin < 0.0f) {                       // negative end jump
            segl[nseg * 32] = ((ull)(unsigned)km << 32) |
                              (ull)__float_as_uint(vmin);
            nseg++;
            const int nk = min(km + 1, n - 1);
            const float ynk = yl[nk * 32];
            yn = yl[min(nk + 1, n - 1) * 32];
            k = km = nk;                         // kp, vmax unchanged
            vmin = ynk;
            umin = lam;
            umax = ynk + lam - vmax;
            cnt_f = 1.0f;
        } else if (umax > 0.0f) {                // positive end jump
            segl[nseg * 32] = ((ull)(unsigned)kp << 32) |
                              (ull)__float_as_uint(vmax);
            nseg++;
            const int nk = min(kp + 1, n - 1);
            const float ynk = yl[nk * 32];
            yn = yl[min(nk + 1, n - 1) * 32];
            k = kp = nk;                         // km, vmin unchanged
            vmax = ynk;
            umax = -lam;
            umin = ynk - lam - vmin;
            cnt_f = 1.0f;
        } else {                                 // finished
            segl[nseg * 32] = ((ull)(unsigned)(n - 1) << 32) |
                (ull)__float_as_uint(fmaf(umin, frcp_fast(cnt_f), vmin));
            nseg++;
            break;
        }
    }

    // ---- sparsemax tau via Michelot on the RLE segments ----
    float tau;
    {
        float sum = 0.0f;
        int prev = -1;
        for (int j = 0; j < nseg; j++) {
            ull w = segl[j * 32];
            int e = (int)(w >> 32);
            sum += (float)(e - prev) * __uint_as_float((unsigned)w);
            prev = e;
        }
        tau = (sum - 1.0f) * (1.0f / (float)NCOLS);
        int c_prev = n;
        for (int it = 0; it < n; it++) {
            float s = 0.0f;
            int   c = 0;
            int   pr = -1;
            for (int j = 0; j < nseg; j++) {
                ull   w = segl[j * 32];
                int   e = (int)(w >> 32);
                float v = __uint_as_float((unsigned)w);
                int len = e - pr; pr = e;
                bool sup = (v > tau);
                s += sup ? (float)len * v : 0.0f;
                c += sup ? len : 0;
            }
            if (c == c_prev) break;
            tau = (s - 1.0f) / (float)c;
            c_prev = c;
        }
    }

    // ---- reconstruct max(val - tau, 0) into ys (prefetched walk) ----
    {
        int j = 0;
        ull w  = segl[0];
        ull wn = segl[32];
        int   e = (int)(w >> 32);
        float v = __uint_as_float((unsigned)w) - tau;
        for (int c = 0; c < n; c++) {
            yl[c * 32] = fmaxf(v, 0.0f);
            const bool adv = ((c + 1) > e);
            j += (int)adv;
            w = adv ? wn : w;
            e = (int)(w >> 32);
            v = __uint_as_float((unsigned)w) - tau;
            wn = segl[min(j + 1, SEG_ENTRIES - 1) * 32];
        }
    }
    __syncwarp();

    // ---- transpose back via staging + coalesced store ----
    float* dst = out + (size_t)rowBase * NCOLS;
    for (int t = 0; t < 16; t++) {
        #pragma unroll
        for (int cl = 0; cl < 32; cl++)
            stage[lane * PADS + cl] = ys[(t * 32 + cl) * 32 + lane];
        __syncwarp();
        #pragma unroll
        for (int i = 0; i < 32; i++)
            dst[i * NCOLS + t * 32 + lane] = stage[i * PADS + lane];
        __syncwarp();
    }
}

extern "C" void kernel_launch(void* const* d_in, const int* in_sizes, int n_in,
                              void* d_out, int out_size) {
    (void)in_sizes; (void)n_in; (void)out_size;
    const float* x   = (const float*)d_in[0];
    float*       out = (float*)d_out;

    cudaFuncSetAttribute(fusedmax_kernel,
                         cudaFuncAttributeMaxDynamicSharedMemorySize,
                         SMEM_BYTES);
    fusedmax_kernel<<<NROWS / ROWS_PER_BLK, ROWS_PER_BLK, SMEM_BYTES>>>(x, out);
}

// round 12
// speedup vs baseline: 2.0990x; 1.0051x over previous
#include <cuda_runtime.h>

// fusedmax(x) = sparsemax(prox_TV1D(x, alpha=1)), row-wise. B=4096, N=512, fp32.
// 128 blocks x 32 threads; lane = row. ys stride-32 (bank = lane), transposes
// via padded staging tile. Condat scan split hot/end; hot loop carries
// precomputed jump thresholds (thr_n/thr_p) so the LDS->predicate head chain
// is minimal; segment store predicated on jump.
// RLE log -> Michelot sparsemax -> prefetched rebuild.

#define NROWS 4096
#define NCOLS 512
#define ROWS_PER_BLK 32
#define PADS 33
#define YS_FLOATS (NCOLS * 32)
#define STAGE_FLOATS (32 * PADS)
#define SEG_ENTRIES 517
#define SEG_OFF (YS_FLOATS + STAGE_FLOATS)
#define SMEM_BYTES ((SEG_OFF) * 4 + SEG_ENTRIES * 32 * 8)

typedef unsigned long long ull;

__device__ __forceinline__ float frcp_fast(float a) {
    float r;
    asm("rcp.approx.f32 %0, %1;" : "=f"(r) : "f"(a));
    return r;
}

__global__ __launch_bounds__(32, 1)
void fusedmax_kernel(const float* __restrict__ x, float* __restrict__ out) {
    extern __shared__ float smem[];
    float* ys    = smem;                         // [NCOLS][32], stride 32
    float* stage = smem + YS_FLOATS;             // [32][PADS]
    ull*   segb  = (ull*)(smem + SEG_OFF);       // [entry][lane]

    const int lane    = threadIdx.x;
    const int rowBase = blockIdx.x * ROWS_PER_BLK;
    const float lam   = 1.0f;
    const int n       = NCOLS;

    // ---- load + transpose via staging tile (both sides conflict-free) ----
    const float* src = x + (size_t)rowBase * NCOLS;
    for (int t = 0; t < 16; t++) {
        #pragma unroll
        for (int i = 0; i < 32; i++)
            stage[i * PADS + lane] = src[i * NCOLS + t * 32 + lane];
        __syncwarp();
        #pragma unroll
        for (int cl = 0; cl < 32; cl++)
            ys[(t * 32 + cl) * 32 + lane] = stage[lane * PADS + cl];
        __syncwarp();
    }

    float* yl   = ys + lane;                     // yl[c*32] == y[c], bank=lane
    ull*   segl = segb + lane;

    // ---- Condat TV1D: hot loop (k < n-1) + end step (k == n-1) ----
    int   k = 0, km = 0, kp = 0;
    float vmin = yl[0] - lam;
    float vmax = vmin + 2.0f * lam;
    float umin = lam, umax = -lam;
    float thr_n = (vmin - umin) - lam;           // neg-jump threshold
    float thr_p = (vmax - umax) + lam;           // pos-jump threshold
    float cnt_f = 1.0f;
    float yn = yl[1 * 32];                       // y[k+1]
    int   nseg = 0;

    while (true) {
        // -------- hot scan: no end-phase logic --------
        while (k < n - 1) {
            const float inv_spec = frcp_fast(cnt_f + 1.0f);
            const float ycur = yn;               // y[k+1]

            const bool neg  = (ycur < thr_n);
            const bool pos  = (!neg) & (ycur > thr_p);
            const bool jump = neg | pos;

            const int nk = neg ? (km + 1) : (pos ? (kp + 1) : (k + 1));
            // nk <= n-1 guaranteed (k <= n-2, km,kp <= k)

            const float ynk = yl[nk * 32];       // == ycur for mid lanes
            yn = yl[(nk + 1) * 32];              // prefetch (nk+1==n reads
                                                 // stage[lane]: dead value)

            // RLE log: predicated store, bump on jump
            if (jump) {
                segl[nseg * 32] =
                    ((ull)(unsigned)(neg ? km : kp) << 32) |
                    (ull)__float_as_uint(pos ? vmax : vmin);
            }
            nseg += (int)jump;

            // mid candidates (register-fed)
            const float inv_cnt = jump ? 1.0f : inv_spec;
            const float umin_t  = umin + ycur - vmin;
            const float umax_t  = umax + ycur - vmax;
            const bool  c1 = (umin_t >= lam);
            const bool  c2 = (umax_t <= -lam);
            const float vmin_mid = c1 ? fmaf(umin_t - lam, inv_cnt, vmin) : vmin;
            const float umin_mid = c1 ? lam : umin_t;
            const int   km_mid   = c1 ? nk : km;
            const float vmax_mid = c2 ? fmaf(umax_t + lam, inv_cnt, vmax) : vmax;
            const float umax_mid = c2 ? -lam : umax_t;
            const int   kp_mid   = c2 ? nk : kp;

            // merge (interior jump: full reset, no end-phase cases)
            vmin = jump ? (neg ? ynk : ynk - 2.0f * lam) : vmin_mid;
            vmax = jump ? (pos ? ynk : ynk + 2.0f * lam) : vmax_mid;
            umin = jump ? lam  : umin_mid;
            umax = jump ? -lam : umax_mid;
            km   = jump ? nk : km_mid;
            kp   = jump ? nk : kp_mid;
            cnt_f = jump ? 1.0f : (cnt_f + 1.0f);
            k    = nk;
            thr_n = (vmin - umin) - lam;         // off-chain (overlaps LDS)
            thr_p = (vmax - umax) + lam;
        }

        // -------- end step: k == n-1 --------
        if (umin < 0.0f) {                       // negative end jump
            segl[nseg * 32] = ((ull)(unsigned)km << 32) |
                              (ull)__float_as_uint(vmin);
            nseg++;
            const int nk = min(km + 1, n - 1);
            const float ynk = yl[nk * 32];
            yn = yl[min(nk + 1, n - 1) * 32];
            k = km = nk;                         // kp, vmax unchanged
            vmin = ynk;
            umin = lam;
            umax = ynk + lam - vmax;
            cnt_f = 1.0f;
            thr_n = (vmin - umin) - lam;
            thr_p = (vmax - umax) + lam;
        } else if (umax > 0.0f) {                // positive end jump
            segl[nseg * 32] = ((ull)(unsigned)kp << 32) |
                              (ull)__float_as_uint(vmax);
            nseg++;
            const int nk = min(kp + 1, n - 1);
            const float ynk = yl[nk * 32];
            yn = yl[min(nk + 1, n - 1) * 32];
            k = kp = nk;                         // km, vmin unchanged
            vmax = ynk;
            umax = -lam;
            umin = ynk - lam - vmin;
            cnt_f = 1.0f;
            thr_n = (vmin - umin) - lam;
            thr_p = (vmax - umax) + lam;
        } else {                                 // finished
            segl[nseg * 32] = ((ull)(unsigned)(n - 1) << 32) |
                (ull)__float_as_uint(fmaf(umin, frcp_fast(cnt_f), vmin));
            nseg++;
            break;
        }
    }

    // ---- sparsemax tau via Michelot on the RLE segments ----
    float tau;
    {
        float sum = 0.0f;
        int prev = -1;
        for (int j = 0; j < nseg; j++) {
            ull w = segl[j * 32];
            int e = (int)(w >> 32);
            sum += (float)(e - prev) * __uint_as_float((unsigned)w);
            prev = e;
        }
        tau = (sum - 1.0f) * (1.0f / (float)NCOLS);
        int c_prev = n;
        for (int it = 0; it < n; it++) {
            float s = 0.0f;
            int   c = 0;
            int   pr = -1;
            for (int j = 0; j < nseg; j++) {
                ull   w = segl[j * 32];
                int   e = (int)(w >> 32);
                float v = __uint_as_float((unsigned)w);
                int len = e - pr; pr = e;
                bool sup = (v > tau);
                s += sup ? (float)len * v : 0.0f;
                c += sup ? len : 0;
            }
            if (c == c_prev) break;
            tau = (s - 1.0f) / (float)c;
            c_prev = c;
        }
    }

    // ---- reconstruct max(val - tau, 0) into ys (prefetched walk) ----
    {
        int j = 0;
        ull w  = segl[0];
        ull wn = segl[32];
        int   e = (int)(w >> 32);
        float v = __uint_as_float((unsigned)w) - tau;
        for (int c = 0; c < n; c++) {
            yl[c * 32] = fmaxf(v, 0.0f);
            const bool adv = ((c + 1) > e);
            j += (int)adv;
            w = adv ? wn : w;
            e = (int)(w >> 32);
            v = __uint_as_float((unsigned)w) - tau;
            wn = segl[min(j + 1, SEG_ENTRIES - 1) * 32];
        }
    }
    __syncwarp();

    // ---- transpose back via staging + coalesced store ----
    float* dst = out + (size_t)rowBase * NCOLS;
    for (int t = 0; t < 16; t++) {
        #pragma unroll
        for (int cl = 0; cl < 32; cl++)
            stage[lane * PADS + cl] = ys[(t * 32 + cl) * 32 + lane];
        __syncwarp();
        #pragma unroll
        for (int i = 0; i < 32; i++)
            dst[i * NCOLS + t * 32 + lane] = stage[i * PADS + lane];
        __syncwarp();
    }
}

extern "C" void kernel_launch(void* const* d_in, const int* in_sizes, int n_in,
                              void* d_out, int out_size) {
    (void)in_sizes; (void)n_in; (void)out_size;
    const float* x   = (const float*)d_in[0];
    float*       out = (float*)d_out;

    cudaFuncSetAttribute(fusedmax_kernel,
                         cudaFuncAttributeMaxDynamicSharedMemorySize,
                         SMEM_BYTES);
    fusedmax_kernel<<<NROWS / ROWS_PER_BLK, ROWS_PER_BLK, SMEM_BYTES>>>(x, out);
}